// round 12
// baseline (speedup 1.0000x reference)
#include <cuda_runtime.h>
#include <cuda_bf16.h>
#include <cuda_fp16.h>

#define EMB 16
#define MAXN 200000

// Scratch (device globals — no allocation allowed)
__device__ uint4  g_left_h[MAXN * 2];    // [N_LEFT, 16] half
__device__ uint4  g_right_h[MAXN * 2];   // [N_RIGHT, 16] half
__device__ float4 g_agg[MAXN * 4];       // [N_RIGHT, 16] fp32 sum of (relu(pre)@Wf.T + bf)

// ---------------------------------------------------------------------------
// Kernel 1: node transforms -> fp16 tables. (R5/R9 proven version)
// ---------------------------------------------------------------------------
__global__ void node_transform_kernel(const float4* __restrict__ left,
                                      const float4* __restrict__ right,
                                      const float4* __restrict__ W_left,
                                      const float* __restrict__ b_left,
                                      const float4* __restrict__ W_right,
                                      int n_left, int n_right) {
    __shared__ float4 sWl[EMB * 4];
    __shared__ float4 sWr[EMB * 4];
    __shared__ float  sbl[EMB];
    for (int i = threadIdx.x; i < EMB * 4; i += blockDim.x) {
        sWl[i] = W_left[i];
        sWr[i] = W_right[i];
    }
    if (threadIdx.x < EMB) sbl[threadIdx.x] = b_left[threadIdx.x];
    __syncthreads();

    int t = blockIdx.x * blockDim.x + threadIdx.x;
    if (t >= n_left + n_right) return;

    bool is_left = (t < n_left);
    int node = is_left ? t : (t - n_left);
    const float4* src = is_left ? (left + (size_t)node * 4) : (right + (size_t)node * 4);
    uint4* dst = is_left ? (g_left_h + (size_t)node * 2) : (g_right_h + (size_t)node * 2);
    const float4* W = is_left ? sWl : sWr;

    float4 x[4];
#pragma unroll
    for (int q = 0; q < 4; q++) x[q] = src[q];

    float y[EMB];
#pragma unroll
    for (int j = 0; j < EMB; j++) {
        float a = is_left ? sbl[j] : 0.0f;
#pragma unroll
        for (int q = 0; q < 4; q++) {
            float4 w = W[j * 4 + q];
            a = fmaf(x[q].x, w.x, a);
            a = fmaf(x[q].y, w.y, a);
            a = fmaf(x[q].z, w.z, a);
            a = fmaf(x[q].w, w.w, a);
        }
        y[j] = a;
    }

#pragma unroll
    for (int h = 0; h < 2; h++) {
        uint4 o;
        __half2 h0 = __floats2half2_rn(y[8 * h + 0], y[8 * h + 1]);
        __half2 h1 = __floats2half2_rn(y[8 * h + 2], y[8 * h + 3]);
        __half2 h2 = __floats2half2_rn(y[8 * h + 4], y[8 * h + 5]);
        __half2 h3 = __floats2half2_rn(y[8 * h + 6], y[8 * h + 7]);
        o.x = *(unsigned int*)&h0;
        o.y = *(unsigned int*)&h1;
        o.z = *(unsigned int*)&h2;
        o.w = *(unsigned int*)&h3;
        dst[h] = o;
    }
}

// ---------------------------------------------------------------------------
// Kernel 2: edge kernel — 2 lanes/edge, W_final FOLDED IN (degree eliminated).
//   lane j computes relu(pre) for channels 8j..8j+7, exchanges halves via
//   shfl.xor(1), applies msg = relu16 @ Wf.T + bf for its 8 output channels,
//   then 2x red.v4.f32 into g_agg. No degree red anywhere.
// ---------------------------------------------------------------------------
__global__ void edge_kernel(const int* __restrict__ eidx,          // [2, E] int32
                            const float* __restrict__ efeat,       // [E]
                            const float4* __restrict__ W_edge4,    // 16 floats
                            const float4* __restrict__ W_final4,   // 256 floats
                            const float* __restrict__ b_final,     // 16 floats
                            int E) {
    __shared__ float4 sWf[64];
    __shared__ float  sbf[16];
    for (int i = threadIdx.x; i < 64; i += blockDim.x) sWf[i] = W_final4[i];
    if (threadIdx.x < 16) sbf[threadIdx.x] = b_final[threadIdx.x];
    __syncthreads();

    long long t = (long long)blockIdx.x * blockDim.x + threadIdx.x;
    int e = (int)(t >> 1);
    if (e >= E) return;
    int j = (int)(t & 1);

    int li = eidx[e];
    int ri = eidx[(size_t)E + e];
    float w = efeat[e];

    uint4 Lu = g_left_h[(size_t)li * 2 + j];
    uint4 Ru = g_right_h[(size_t)ri * 2 + j];
    float4 We0 = W_edge4[2 * j];
    float4 We1 = W_edge4[2 * j + 1];

    float2 l0 = __half22float2(*(__half2*)&Lu.x);
    float2 l1 = __half22float2(*(__half2*)&Lu.y);
    float2 l2 = __half22float2(*(__half2*)&Lu.z);
    float2 l3 = __half22float2(*(__half2*)&Lu.w);
    float2 r0 = __half22float2(*(__half2*)&Ru.x);
    float2 r1 = __half22float2(*(__half2*)&Ru.y);
    float2 r2 = __half22float2(*(__half2*)&Ru.z);
    float2 r3 = __half22float2(*(__half2*)&Ru.w);

    // relu(pre) for this lane's 8 channels (channels 8j .. 8j+7)
    float p[8];
    p[0] = fmaxf(fmaf(w, We0.x, l0.x + r0.x), 0.0f);
    p[1] = fmaxf(fmaf(w, We0.y, l0.y + r0.y), 0.0f);
    p[2] = fmaxf(fmaf(w, We0.z, l1.x + r1.x), 0.0f);
    p[3] = fmaxf(fmaf(w, We0.w, l1.y + r1.y), 0.0f);
    p[4] = fmaxf(fmaf(w, We1.x, l2.x + r2.x), 0.0f);
    p[5] = fmaxf(fmaf(w, We1.y, l2.y + r2.y), 0.0f);
    p[6] = fmaxf(fmaf(w, We1.z, l3.x + r3.x), 0.0f);
    p[7] = fmaxf(fmaf(w, We1.w, l3.y + r3.y), 0.0f);

    // exchange halves with partner lane (same edge, lane j^1)
    unsigned mask = __activemask();
    float f[16];
#pragma unroll
    for (int i = 0; i < 8; i++) {
        float o = __shfl_xor_sync(mask, p[i], 1);
        f[8 * j + i] = p[i];
        f[8 * (1 - j) + i] = o;
    }

    // msg channels c = 8j .. 8j+7:  msg_c = bf[c] + sum_k Wf[c][k] * f[k]
    float o[8];
#pragma unroll
    for (int c8 = 0; c8 < 8; c8++) {
        int c = 8 * j + c8;
        float acc = sbf[c];
#pragma unroll
        for (int q = 0; q < 4; q++) {
            float4 wv = sWf[c * 4 + q];
            acc = fmaf(f[4 * q + 0], wv.x, acc);
            acc = fmaf(f[4 * q + 1], wv.y, acc);
            acc = fmaf(f[4 * q + 2], wv.z, acc);
            acc = fmaf(f[4 * q + 3], wv.w, acc);
        }
        o[c8] = acc;
    }

    float4* dst = g_agg + (size_t)ri * 4 + 2 * j;
    asm volatile("red.global.add.v4.f32 [%0], {%1, %2, %3, %4};"
                 :: "l"(dst), "f"(o[0]), "f"(o[1]), "f"(o[2]), "f"(o[3])
                 : "memory");
    asm volatile("red.global.add.v4.f32 [%0], {%1, %2, %3, %4};"
                 :: "l"(dst + 1), "f"(o[4]), "f"(o[5]), "f"(o[6]), "f"(o[7])
                 : "memory");
}

// ---------------------------------------------------------------------------
// Kernel 3: per-right-node tail. g_agg IS aggregated already (Wf folded in).
//   post = relu(agg) @ W_post.T + b_post ; cat ; W_out1 ; W_out2.
// ---------------------------------------------------------------------------
__global__ void post_kernel(const float4* __restrict__ rightf,
                            const float4* __restrict__ W_post,  const float* __restrict__ b_post,
                            const float4* __restrict__ W_out1,  const float* __restrict__ b_out1,
                            const float4* __restrict__ W_out2,  const float* __restrict__ b_out2,
                            float4* __restrict__ out, int n_right) {
    __shared__ float4 sWp[64], sW1[128], sW2[64];
    __shared__ float  sbp[16], sb1[16], sb2[16];
    for (int i = threadIdx.x; i < 64; i += blockDim.x) {
        sWp[i] = W_post[i];
        sW2[i] = W_out2[i];
    }
    for (int i = threadIdx.x; i < 128; i += blockDim.x) sW1[i] = W_out1[i];
    if (threadIdx.x < 16) {
        sbp[threadIdx.x] = b_post[threadIdx.x];
        sb1[threadIdx.x] = b_out1[threadIdx.x];
        sb2[threadIdx.x] = b_out2[threadIdx.x];
    }
    __syncthreads();

    int rr = blockIdx.x * blockDim.x + threadIdx.x;
    if (rr >= n_right) return;

    // a = relu(aggregated)  (aggregated = g_agg directly)
    float4 a[4];
#pragma unroll
    for (int q = 0; q < 4; q++) {
        float4 v = g_agg[(size_t)rr * 4 + q];
        a[q].x = fmaxf(v.x, 0.0f);
        a[q].y = fmaxf(v.y, 0.0f);
        a[q].z = fmaxf(v.z, 0.0f);
        a[q].w = fmaxf(v.w, 0.0f);
    }

    // post = a @ W_post.T + b_post -> first half of cat
    float4 cat[8];
#pragma unroll
    for (int q = 0; q < 4; q++) {
        float t[4];
#pragma unroll
        for (int c = 0; c < 4; c++) {
            int j = 4 * q + c;
            float acc = sbp[j];
#pragma unroll
            for (int p = 0; p < 4; p++) {
                float4 wv = sWp[j * 4 + p];
                acc = fmaf(a[p].x, wv.x, acc);
                acc = fmaf(a[p].y, wv.y, acc);
                acc = fmaf(a[p].z, wv.z, acc);
                acc = fmaf(a[p].w, wv.w, acc);
            }
            t[c] = acc;
        }
        cat[q].x = t[0]; cat[q].y = t[1]; cat[q].z = t[2]; cat[q].w = t[3];
    }
#pragma unroll
    for (int q = 0; q < 4; q++) cat[4 + q] = rightf[(size_t)rr * 4 + q];

    // h = relu(cat @ W_out1.T + b_out1)
    float4 h[4];
#pragma unroll
    for (int q = 0; q < 4; q++) {
        float t[4];
#pragma unroll
        for (int c = 0; c < 4; c++) {
            int j = 4 * q + c;
            float acc = sb1[j];
#pragma unroll
            for (int p = 0; p < 8; p++) {
                float4 wv = sW1[j * 8 + p];
                acc = fmaf(cat[p].x, wv.x, acc);
                acc = fmaf(cat[p].y, wv.y, acc);
                acc = fmaf(cat[p].z, wv.z, acc);
                acc = fmaf(cat[p].w, wv.w, acc);
            }
            t[c] = fmaxf(acc, 0.0f);
        }
        h[q].x = t[0]; h[q].y = t[1]; h[q].z = t[2]; h[q].w = t[3];
    }

    // out = h @ W_out2.T + b_out2
#pragma unroll
    for (int q = 0; q < 4; q++) {
        float t[4];
#pragma unroll
        for (int c = 0; c < 4; c++) {
            int j = 4 * q + c;
            float acc = sb2[j];
#pragma unroll
            for (int p = 0; p < 4; p++) {
                float4 wv = sW2[j * 4 + p];
                acc = fmaf(h[p].x, wv.x, acc);
                acc = fmaf(h[p].y, wv.y, acc);
                acc = fmaf(h[p].z, wv.z, acc);
                acc = fmaf(h[p].w, wv.w, acc);
            }
            t[c] = acc;
        }
        float4 y;
        y.x = t[0]; y.y = t[1]; y.z = t[2]; y.w = t[3];
        out[(size_t)rr * 4 + q] = y;
    }
}

// ---------------------------------------------------------------------------
extern "C" void kernel_launch(void* const* d_in, const int* in_sizes, int n_in,
                              void* d_out, int out_size) {
    const float* left    = (const float*)d_in[0];
    const float* efeat   = (const float*)d_in[1];
    const float* right   = (const float*)d_in[2];
    const int*   eidx    = (const int*)d_in[3];   // int32: JAX x64 disabled
    const float* W_left  = (const float*)d_in[4];
    const float* b_left  = (const float*)d_in[5];
    const float* W_edge  = (const float*)d_in[6];
    const float* W_right = (const float*)d_in[7];
    const float* W_final = (const float*)d_in[8];
    const float* b_final = (const float*)d_in[9];
    const float* W_post  = (const float*)d_in[10];
    const float* b_post  = (const float*)d_in[11];
    const float* W_out1  = (const float*)d_in[12];
    const float* b_out1  = (const float*)d_in[13];
    const float* W_out2  = (const float*)d_in[14];
    const float* b_out2  = (const float*)d_in[15];
    float* out = (float*)d_out;

    int n_left  = in_sizes[0] / EMB;
    int n_right = in_sizes[2] / EMB;
    int E       = in_sizes[1];

    void* agg_p = nullptr;
    cudaGetSymbolAddress(&agg_p, g_agg);
    cudaMemsetAsync(agg_p, 0, (size_t)n_right * EMB * sizeof(float));

    int total_nodes = n_left + n_right;
    node_transform_kernel<<<(total_nodes + 255) / 256, 256>>>(
        (const float4*)left, (const float4*)right, (const float4*)W_left, b_left,
        (const float4*)W_right, n_left, n_right);

    long long edge_threads = (long long)E * 2;
    int edge_blocks = (int)((edge_threads + 255) / 256);
    edge_kernel<<<edge_blocks, 256>>>(eidx, efeat, (const float4*)W_edge,
                                      (const float4*)W_final, b_final, E);

    post_kernel<<<(n_right + 255) / 256, 256>>>(
        (const float4*)right,
        (const float4*)W_post,  b_post,
        (const float4*)W_out1,  b_out1,
        (const float4*)W_out2,  b_out2,
        (float4*)out, n_right);
}

// round 14
// speedup vs baseline: 1.5597x; 1.5597x over previous
#include <cuda_runtime.h>
#include <cuda_bf16.h>
#include <cuda_fp16.h>

#define EMB 16
#define MAXN 200000

// Scratch (device globals — no allocation allowed)
__device__ uint4  g_left_h[MAXN * 2];    // [N_LEFT, 16] half
__device__ uint4  g_right_h[MAXN * 2];   // [N_RIGHT, 16] half
__device__ float4 g_agg[MAXN * 4];       // [N_RIGHT, 16] fp32 sum of relu(pre)
__device__ float  g_deg[MAXN];           // per-right-node degree (float)
__device__ float  g_Wc[EMB * EMB];       // W1a @ W_post  (folded)
__device__ float  g_bc[EMB];             // W1a @ b_post + b_out1

// ---------------------------------------------------------------------------
// Kernel 0: fold W_post into W_out1's first half.  One tiny block.
//   Wc[j][k] = sum_m W_out1[j][m] * W_post[m][k]   (m over first 16 cols of W_out1)
//   bc[j]    = b_out1[j] + sum_m W_out1[j][m] * b_post[m]
// ---------------------------------------------------------------------------
__global__ void fold_kernel(const float* __restrict__ W_post,
                            const float* __restrict__ b_post,
                            const float* __restrict__ W_out1,   // [16][32]
                            const float* __restrict__ b_out1) {
    int tid = threadIdx.x;          // 256 threads: (j,k)
    int j = tid >> 4;
    int k = tid & 15;
    float acc = 0.0f;
#pragma unroll
    for (int m = 0; m < EMB; m++)
        acc = fmaf(W_out1[j * 32 + m], W_post[m * EMB + k], acc);
    g_Wc[j * EMB + k] = acc;
    if (k == 0) {
        float b = b_out1[j];
#pragma unroll
        for (int m = 0; m < EMB; m++)
            b = fmaf(W_out1[j * 32 + m], b_post[m], b);
        g_bc[j] = b;
    }
}

// ---------------------------------------------------------------------------
// Kernel 1: node transforms -> fp16 tables. (R5/R9 proven version)
// ---------------------------------------------------------------------------
__global__ void node_transform_kernel(const float4* __restrict__ left,
                                      const float4* __restrict__ right,
                                      const float4* __restrict__ W_left,
                                      const float* __restrict__ b_left,
                                      const float4* __restrict__ W_right,
                                      int n_left, int n_right) {
    __shared__ float4 sWl[EMB * 4];
    __shared__ float4 sWr[EMB * 4];
    __shared__ float  sbl[EMB];
    for (int i = threadIdx.x; i < EMB * 4; i += blockDim.x) {
        sWl[i] = W_left[i];
        sWr[i] = W_right[i];
    }
    if (threadIdx.x < EMB) sbl[threadIdx.x] = b_left[threadIdx.x];
    __syncthreads();

    int t = blockIdx.x * blockDim.x + threadIdx.x;
    if (t >= n_left + n_right) return;

    bool is_left = (t < n_left);
    int node = is_left ? t : (t - n_left);
    const float4* src = is_left ? (left + (size_t)node * 4) : (right + (size_t)node * 4);
    uint4* dst = is_left ? (g_left_h + (size_t)node * 2) : (g_right_h + (size_t)node * 2);
    const float4* W = is_left ? sWl : sWr;

    float4 x[4];
#pragma unroll
    for (int q = 0; q < 4; q++) x[q] = src[q];

    float y[EMB];
#pragma unroll
    for (int j = 0; j < EMB; j++) {
        float a = is_left ? sbl[j] : 0.0f;
#pragma unroll
        for (int q = 0; q < 4; q++) {
            float4 w = W[j * 4 + q];
            a = fmaf(x[q].x, w.x, a);
            a = fmaf(x[q].y, w.y, a);
            a = fmaf(x[q].z, w.z, a);
            a = fmaf(x[q].w, w.w, a);
        }
        y[j] = a;
    }

#pragma unroll
    for (int h = 0; h < 2; h++) {
        uint4 o;
        __half2 h0 = __floats2half2_rn(y[8 * h + 0], y[8 * h + 1]);
        __half2 h1 = __floats2half2_rn(y[8 * h + 2], y[8 * h + 3]);
        __half2 h2 = __floats2half2_rn(y[8 * h + 4], y[8 * h + 5]);
        __half2 h3 = __floats2half2_rn(y[8 * h + 6], y[8 * h + 7]);
        o.x = *(unsigned int*)&h0;
        o.y = *(unsigned int*)&h1;
        o.z = *(unsigned int*)&h2;
        o.w = *(unsigned int*)&h3;
        dst[h] = o;
    }
}

// ---------------------------------------------------------------------------
// Kernel 2: edge kernel — EXACT R5/R9 structure (empirically fastest).
// ---------------------------------------------------------------------------
__global__ void edge_kernel(const int* __restrict__ eidx,          // [2, E] int32
                            const float* __restrict__ efeat,       // [E]
                            const float4* __restrict__ W_edge4,    // 16 floats
                            int E) {
    long long t = (long long)blockIdx.x * blockDim.x + threadIdx.x;
    int e = (int)(t >> 1);
    if (e >= E) return;
    int j = (int)(t & 1);

    int li = eidx[e];
    int ri = eidx[(size_t)E + e];
    float w = efeat[e];

    uint4 Lu = g_left_h[(size_t)li * 2 + j];
    uint4 Ru = g_right_h[(size_t)ri * 2 + j];
    float4 We0 = W_edge4[2 * j];
    float4 We1 = W_edge4[2 * j + 1];

    float2 l0 = __half22float2(*(__half2*)&Lu.x);
    float2 l1 = __half22float2(*(__half2*)&Lu.y);
    float2 l2 = __half22float2(*(__half2*)&Lu.z);
    float2 l3 = __half22float2(*(__half2*)&Lu.w);
    float2 r0 = __half22float2(*(__half2*)&Ru.x);
    float2 r1 = __half22float2(*(__half2*)&Ru.y);
    float2 r2 = __half22float2(*(__half2*)&Ru.z);
    float2 r3 = __half22float2(*(__half2*)&Ru.w);

    float p0 = fmaxf(fmaf(w, We0.x, l0.x + r0.x), 0.0f);
    float p1 = fmaxf(fmaf(w, We0.y, l0.y + r0.y), 0.0f);
    float p2 = fmaxf(fmaf(w, We0.z, l1.x + r1.x), 0.0f);
    float p3 = fmaxf(fmaf(w, We0.w, l1.y + r1.y), 0.0f);
    float p4 = fmaxf(fmaf(w, We1.x, l2.x + r2.x), 0.0f);
    float p5 = fmaxf(fmaf(w, We1.y, l2.y + r2.y), 0.0f);
    float p6 = fmaxf(fmaf(w, We1.z, l3.x + r3.x), 0.0f);
    float p7 = fmaxf(fmaf(w, We1.w, l3.y + r3.y), 0.0f);

    float4* dst = g_agg + (size_t)ri * 4 + 2 * j;
    asm volatile("red.global.add.v4.f32 [%0], {%1, %2, %3, %4};"
                 :: "l"(dst), "f"(p0), "f"(p1), "f"(p2), "f"(p3)
                 : "memory");
    asm volatile("red.global.add.v4.f32 [%0], {%1, %2, %3, %4};"
                 :: "l"(dst + 1), "f"(p4), "f"(p5), "f"(p6), "f"(p7)
                 : "memory");
    if (j == 0) {
        asm volatile("red.global.add.f32 [%0], %1;"
                     :: "l"(g_deg + ri), "f"(1.0f)
                     : "memory");
    }
}

// ---------------------------------------------------------------------------
// Kernel 3: per-right-node tail, W_post FOLDED into W_out1 (3 stages not 4):
//   a   = relu(agg @ Wf.T + d*bf)
//   h   = relu(a @ Wc.T + right @ W1b.T + bc)
//   out = h @ W2.T + b2
// ---------------------------------------------------------------------------
__global__ __launch_bounds__(128)
void post_kernel(const float4* __restrict__ rightf,
                 const float4* __restrict__ W_final, const float* __restrict__ b_final,
                 const float* __restrict__ W_out1,   // [16][32] raw (for W1b half)
                 const float4* __restrict__ W_out2,  const float* __restrict__ b_out2,
                 float4* __restrict__ out, int n_right) {
    __shared__ float4 sWf[64], sWc[64], sW1b[64], sW2[64];
    __shared__ float  sbf[16], sbc[16], sb2[16];
    for (int i = threadIdx.x; i < 64; i += blockDim.x) {
        sWf[i] = W_final[i];
        sWc[i] = *(const float4*)&g_Wc[i * 4];
        sW2[i] = W_out2[i];
        // W1b[j][m] = W_out1[j*32 + 16 + m]; as float4: row j, quarter q
        int j = i >> 2, q = i & 3;
        sW1b[i] = *(const float4*)&W_out1[j * 32 + 16 + q * 4];
    }
    if (threadIdx.x < 16) {
        sbf[threadIdx.x] = b_final[threadIdx.x];
        sbc[threadIdx.x] = g_bc[threadIdx.x];
        sb2[threadIdx.x] = b_out2[threadIdx.x];
    }
    __syncthreads();

    int rr = blockIdx.x * blockDim.x + threadIdx.x;
    if (rr >= n_right) return;

    float4 S[4];
#pragma unroll
    for (int q = 0; q < 4; q++) S[q] = g_agg[(size_t)rr * 4 + q];
    float d = g_deg[rr];

    float4 R[4];
#pragma unroll
    for (int q = 0; q < 4; q++) R[q] = rightf[(size_t)rr * 4 + q];

    // a = relu(S @ Wf.T + d*bf)
    float4 a[4];
#pragma unroll
    for (int q = 0; q < 4; q++) {
        float t[4];
#pragma unroll
        for (int c = 0; c < 4; c++) {
            int j = 4 * q + c;
            float acc = d * sbf[j];
#pragma unroll
            for (int p = 0; p < 4; p++) {
                float4 wv = sWf[j * 4 + p];
                acc = fmaf(S[p].x, wv.x, acc);
                acc = fmaf(S[p].y, wv.y, acc);
                acc = fmaf(S[p].z, wv.z, acc);
                acc = fmaf(S[p].w, wv.w, acc);
            }
            t[c] = fmaxf(acc, 0.0f);
        }
        a[q].x = t[0]; a[q].y = t[1]; a[q].z = t[2]; a[q].w = t[3];
    }

    // h = relu(a @ Wc.T + R @ W1b.T + bc)
    float4 h[4];
#pragma unroll
    for (int q = 0; q < 4; q++) {
        float t[4];
#pragma unroll
        for (int c = 0; c < 4; c++) {
            int j = 4 * q + c;
            float acc = sbc[j];
#pragma unroll
            for (int p = 0; p < 4; p++) {
                float4 wv = sWc[j * 4 + p];
                acc = fmaf(a[p].x, wv.x, acc);
                acc = fmaf(a[p].y, wv.y, acc);
                acc = fmaf(a[p].z, wv.z, acc);
                acc = fmaf(a[p].w, wv.w, acc);
            }
#pragma unroll
            for (int p = 0; p < 4; p++) {
                float4 wv = sW1b[j * 4 + p];
                acc = fmaf(R[p].x, wv.x, acc);
                acc = fmaf(R[p].y, wv.y, acc);
                acc = fmaf(R[p].z, wv.z, acc);
                acc = fmaf(R[p].w, wv.w, acc);
            }
            t[c] = fmaxf(acc, 0.0f);
        }
        h[q].x = t[0]; h[q].y = t[1]; h[q].z = t[2]; h[q].w = t[3];
    }

    // out = h @ W2.T + b2
#pragma unroll
    for (int q = 0; q < 4; q++) {
        float t[4];
#pragma unroll
        for (int c = 0; c < 4; c++) {
            int j = 4 * q + c;
            float acc = sb2[j];
#pragma unroll
            for (int p = 0; p < 4; p++) {
                float4 wv = sW2[j * 4 + p];
                acc = fmaf(h[p].x, wv.x, acc);
                acc = fmaf(h[p].y, wv.y, acc);
                acc = fmaf(h[p].z, wv.z, acc);
                acc = fmaf(h[p].w, wv.w, acc);
            }
            t[c] = acc;
        }
        float4 y;
        y.x = t[0]; y.y = t[1]; y.z = t[2]; y.w = t[3];
        out[(size_t)rr * 4 + q] = y;
    }
}

// ---------------------------------------------------------------------------
extern "C" void kernel_launch(void* const* d_in, const int* in_sizes, int n_in,
                              void* d_out, int out_size) {
    const float* left    = (const float*)d_in[0];
    const float* efeat   = (const float*)d_in[1];
    const float* right   = (const float*)d_in[2];
    const int*   eidx    = (const int*)d_in[3];   // int32: JAX x64 disabled
    const float* W_left  = (const float*)d_in[4];
    const float* b_left  = (const float*)d_in[5];
    const float* W_edge  = (const float*)d_in[6];
    const float* W_right = (const float*)d_in[7];
    const float* W_final = (const float*)d_in[8];
    const float* b_final = (const float*)d_in[9];
    const float* W_post  = (const float*)d_in[10];
    const float* b_post  = (const float*)d_in[11];
    const float* W_out1  = (const float*)d_in[12];
    const float* b_out1  = (const float*)d_in[13];
    const float* W_out2  = (const float*)d_in[14];
    const float* b_out2  = (const float*)d_in[15];
    float* out = (float*)d_out;

    int n_left  = in_sizes[0] / EMB;
    int n_right = in_sizes[2] / EMB;
    int E       = in_sizes[1];

    void* agg_p = nullptr;
    void* deg_p = nullptr;
    cudaGetSymbolAddress(&agg_p, g_agg);
    cudaGetSymbolAddress(&deg_p, g_deg);
    cudaMemsetAsync(agg_p, 0, (size_t)n_right * EMB * sizeof(float));
    cudaMemsetAsync(deg_p, 0, (size_t)n_right * sizeof(float));

    fold_kernel<<<1, 256>>>(W_post, b_post, W_out1, b_out1);

    int total_nodes = n_left + n_right;
    node_transform_kernel<<<(total_nodes + 255) / 256, 256>>>(
        (const float4*)left, (const float4*)right, (const float4*)W_left, b_left,
        (const float4*)W_right, n_left, n_right);

    long long edge_threads = (long long)E * 2;
    int edge_blocks = (int)((edge_threads + 255) / 256);
    edge_kernel<<<edge_blocks, 256>>>(eidx, efeat, (const float4*)W_edge, E);

    post_kernel<<<(n_right + 127) / 128, 128>>>(
        (const float4*)right,
        (const float4*)W_final, b_final,
        W_out1,
        (const float4*)W_out2, b_out2,
        (float4*)out, n_right);
}

// round 15
// speedup vs baseline: 1.6227x; 1.0404x over previous
#include <cuda_runtime.h>
#include <cuda_bf16.h>
#include <cuda_fp16.h>

#define EMB 16
#define MAXN 200000

// Scratch (device globals — no allocation allowed)
__device__ uint4  g_left_h[MAXN * 2];    // [N_LEFT, 16] half
__device__ uint4  g_right_h[MAXN * 2];   // [N_RIGHT, 16] half
__device__ float4 g_agg[MAXN * 4];       // [N_RIGHT, 16] fp32 sum of relu(pre)
__device__ float  g_deg[MAXN];           // per-right-node degree (float)
__device__ float  g_Wc[EMB * EMB];       // W1a @ W_post  (folded)
__device__ float  g_bc[EMB];             // W1a @ b_post + b_out1

// ---------------------------------------------------------------------------
// Kernel 1 (fused): node transforms -> fp16 tables
//                   + zero-init of g_agg/g_deg (extra thread range)
//                   + weight fold Wc/bc (block 0).
// ---------------------------------------------------------------------------
__global__ void node_transform_kernel(const float4* __restrict__ left,
                                      const float4* __restrict__ right,
                                      const float4* __restrict__ W_left,
                                      const float* __restrict__ b_left,
                                      const float4* __restrict__ W_right,
                                      const float* __restrict__ W_post,
                                      const float* __restrict__ b_post,
                                      const float* __restrict__ W_out1,
                                      const float* __restrict__ b_out1,
                                      int n_left, int n_right) {
    __shared__ float4 sWl[EMB * 4];
    __shared__ float4 sWr[EMB * 4];
    __shared__ float  sbl[EMB];
    for (int i = threadIdx.x; i < EMB * 4; i += blockDim.x) {
        sWl[i] = W_left[i];
        sWr[i] = W_right[i];
    }
    if (threadIdx.x < EMB) sbl[threadIdx.x] = b_left[threadIdx.x];
    __syncthreads();

    // Fold (block 0 only): Wc = W1a @ W_post ; bc = W1a @ b_post + b_out1
    if (blockIdx.x == 0) {
        int tid = threadIdx.x;           // 256 threads: (j,k)
        int j = tid >> 4;
        int k = tid & 15;
        float acc = 0.0f;
#pragma unroll
        for (int m = 0; m < EMB; m++)
            acc = fmaf(W_out1[j * 32 + m], W_post[m * EMB + k], acc);
        g_Wc[j * EMB + k] = acc;
        if (k == 0) {
            float b = b_out1[j];
#pragma unroll
            for (int m = 0; m < EMB; m++)
                b = fmaf(W_out1[j * 32 + m], b_post[m], b);
            g_bc[j] = b;
        }
    }

    int total_nodes = n_left + n_right;
    int t = blockIdx.x * blockDim.x + threadIdx.x;

    if (t >= total_nodes) {
        // zero-init range: one thread per right node
        int z = t - total_nodes;
        if (z < n_right) {
            float4 zero = make_float4(0.0f, 0.0f, 0.0f, 0.0f);
            float4* ap = g_agg + (size_t)z * 4;
            ap[0] = zero; ap[1] = zero; ap[2] = zero; ap[3] = zero;
            g_deg[z] = 0.0f;
        }
        return;
    }

    bool is_left = (t < n_left);
    int node = is_left ? t : (t - n_left);
    const float4* src = is_left ? (left + (size_t)node * 4) : (right + (size_t)node * 4);
    uint4* dst = is_left ? (g_left_h + (size_t)node * 2) : (g_right_h + (size_t)node * 2);
    const float4* W = is_left ? sWl : sWr;

    float4 x[4];
#pragma unroll
    for (int q = 0; q < 4; q++) x[q] = src[q];

    float y[EMB];
#pragma unroll
    for (int j = 0; j < EMB; j++) {
        float a = is_left ? sbl[j] : 0.0f;
#pragma unroll
        for (int q = 0; q < 4; q++) {
            float4 w = W[j * 4 + q];
            a = fmaf(x[q].x, w.x, a);
            a = fmaf(x[q].y, w.y, a);
            a = fmaf(x[q].z, w.z, a);
            a = fmaf(x[q].w, w.w, a);
        }
        y[j] = a;
    }

#pragma unroll
    for (int h = 0; h < 2; h++) {
        uint4 o;
        __half2 h0 = __floats2half2_rn(y[8 * h + 0], y[8 * h + 1]);
        __half2 h1 = __floats2half2_rn(y[8 * h + 2], y[8 * h + 3]);
        __half2 h2 = __floats2half2_rn(y[8 * h + 4], y[8 * h + 5]);
        __half2 h3 = __floats2half2_rn(y[8 * h + 6], y[8 * h + 7]);
        o.x = *(unsigned int*)&h0;
        o.y = *(unsigned int*)&h1;
        o.z = *(unsigned int*)&h2;
        o.w = *(unsigned int*)&h3;
        dst[h] = o;
    }
}

// ---------------------------------------------------------------------------
// Kernel 2: edge kernel — EXACT R5/R9 structure (empirically fastest).
// ---------------------------------------------------------------------------
__global__ void edge_kernel(const int* __restrict__ eidx,          // [2, E] int32
                            const float* __restrict__ efeat,       // [E]
                            const float4* __restrict__ W_edge4,    // 16 floats
                            int E) {
    long long t = (long long)blockIdx.x * blockDim.x + threadIdx.x;
    int e = (int)(t >> 1);
    if (e >= E) return;
    int j = (int)(t & 1);

    int li = eidx[e];
    int ri = eidx[(size_t)E + e];
    float w = efeat[e];

    uint4 Lu = g_left_h[(size_t)li * 2 + j];
    uint4 Ru = g_right_h[(size_t)ri * 2 + j];
    float4 We0 = W_edge4[2 * j];
    float4 We1 = W_edge4[2 * j + 1];

    float2 l0 = __half22float2(*(__half2*)&Lu.x);
    float2 l1 = __half22float2(*(__half2*)&Lu.y);
    float2 l2 = __half22float2(*(__half2*)&Lu.z);
    float2 l3 = __half22float2(*(__half2*)&Lu.w);
    float2 r0 = __half22float2(*(__half2*)&Ru.x);
    float2 r1 = __half22float2(*(__half2*)&Ru.y);
    float2 r2 = __half22float2(*(__half2*)&Ru.z);
    float2 r3 = __half22float2(*(__half2*)&Ru.w);

    float p0 = fmaxf(fmaf(w, We0.x, l0.x + r0.x), 0.0f);
    float p1 = fmaxf(fmaf(w, We0.y, l0.y + r0.y), 0.0f);
    float p2 = fmaxf(fmaf(w, We0.z, l1.x + r1.x), 0.0f);
    float p3 = fmaxf(fmaf(w, We0.w, l1.y + r1.y), 0.0f);
    float p4 = fmaxf(fmaf(w, We1.x, l2.x + r2.x), 0.0f);
    float p5 = fmaxf(fmaf(w, We1.y, l2.y + r2.y), 0.0f);
    float p6 = fmaxf(fmaf(w, We1.z, l3.x + r3.x), 0.0f);
    float p7 = fmaxf(fmaf(w, We1.w, l3.y + r3.y), 0.0f);

    float4* dst = g_agg + (size_t)ri * 4 + 2 * j;
    asm volatile("red.global.add.v4.f32 [%0], {%1, %2, %3, %4};"
                 :: "l"(dst), "f"(p0), "f"(p1), "f"(p2), "f"(p3)
                 : "memory");
    asm volatile("red.global.add.v4.f32 [%0], {%1, %2, %3, %4};"
                 :: "l"(dst + 1), "f"(p4), "f"(p5), "f"(p6), "f"(p7)
                 : "memory");
    if (j == 0) {
        asm volatile("red.global.add.f32 [%0], %1;"
                     :: "l"(g_deg + ri), "f"(1.0f)
                     : "memory");
    }
}

// ---------------------------------------------------------------------------
// Kernel 3: per-right-node tail (R14 proven: W_post folded, 3 stages).
//   a   = relu(agg @ Wf.T + d*bf)
//   h   = relu(a @ Wc.T + right @ W1b.T + bc)
//   out = h @ W2.T + b2
// ---------------------------------------------------------------------------
__global__ __launch_bounds__(128)
void post_kernel(const float4* __restrict__ rightf,
                 const float4* __restrict__ W_final, const float* __restrict__ b_final,
                 const float* __restrict__ W_out1,   // [16][32] raw (for W1b half)
                 const float4* __restrict__ W_out2,  const float* __restrict__ b_out2,
                 float4* __restrict__ out, int n_right) {
    __shared__ float4 sWf[64], sWc[64], sW1b[64], sW2[64];
    __shared__ float  sbf[16], sbc[16], sb2[16];
    for (int i = threadIdx.x; i < 64; i += blockDim.x) {
        sWf[i] = W_final[i];
        sWc[i] = *(const float4*)&g_Wc[i * 4];
        sW2[i] = W_out2[i];
        int j = i >> 2, q = i & 3;
        sW1b[i] = *(const float4*)&W_out1[j * 32 + 16 + q * 4];
    }
    if (threadIdx.x < 16) {
        sbf[threadIdx.x] = b_final[threadIdx.x];
        sbc[threadIdx.x] = g_bc[threadIdx.x];
        sb2[threadIdx.x] = b_out2[threadIdx.x];
    }
    __syncthreads();

    int rr = blockIdx.x * blockDim.x + threadIdx.x;
    if (rr >= n_right) return;

    float4 S[4];
#pragma unroll
    for (int q = 0; q < 4; q++) S[q] = g_agg[(size_t)rr * 4 + q];
    float d = g_deg[rr];

    float4 R[4];
#pragma unroll
    for (int q = 0; q < 4; q++) R[q] = rightf[(size_t)rr * 4 + q];

    // a = relu(S @ Wf.T + d*bf)
    float4 a[4];
#pragma unroll
    for (int q = 0; q < 4; q++) {
        float t[4];
#pragma unroll
        for (int c = 0; c < 4; c++) {
            int j = 4 * q + c;
            float acc = d * sbf[j];
#pragma unroll
            for (int p = 0; p < 4; p++) {
                float4 wv = sWf[j * 4 + p];
                acc = fmaf(S[p].x, wv.x, acc);
                acc = fmaf(S[p].y, wv.y, acc);
                acc = fmaf(S[p].z, wv.z, acc);
                acc = fmaf(S[p].w, wv.w, acc);
            }
            t[c] = fmaxf(acc, 0.0f);
        }
        a[q].x = t[0]; a[q].y = t[1]; a[q].z = t[2]; a[q].w = t[3];
    }

    // h = relu(a @ Wc.T + R @ W1b.T + bc)
    float4 h[4];
#pragma unroll
    for (int q = 0; q < 4; q++) {
        float t[4];
#pragma unroll
        for (int c = 0; c < 4; c++) {
            int j = 4 * q + c;
            float acc = sbc[j];
#pragma unroll
            for (int p = 0; p < 4; p++) {
                float4 wv = sWc[j * 4 + p];
                acc = fmaf(a[p].x, wv.x, acc);
                acc = fmaf(a[p].y, wv.y, acc);
                acc = fmaf(a[p].z, wv.z, acc);
                acc = fmaf(a[p].w, wv.w, acc);
            }
#pragma unroll
            for (int p = 0; p < 4; p++) {
                float4 wv = sW1b[j * 4 + p];
                acc = fmaf(R[p].x, wv.x, acc);
                acc = fmaf(R[p].y, wv.y, acc);
                acc = fmaf(R[p].z, wv.z, acc);
                acc = fmaf(R[p].w, wv.w, acc);
            }
            t[c] = fmaxf(acc, 0.0f);
        }
        h[q].x = t[0]; h[q].y = t[1]; h[q].z = t[2]; h[q].w = t[3];
    }

    // out = h @ W2.T + b2
#pragma unroll
    for (int q = 0; q < 4; q++) {
        float t[4];
#pragma unroll
        for (int c = 0; c < 4; c++) {
            int j = 4 * q + c;
            float acc = sb2[j];
#pragma unroll
            for (int p = 0; p < 4; p++) {
                float4 wv = sW2[j * 4 + p];
                acc = fmaf(h[p].x, wv.x, acc);
                acc = fmaf(h[p].y, wv.y, acc);
                acc = fmaf(h[p].z, wv.z, acc);
                acc = fmaf(h[p].w, wv.w, acc);
            }
            t[c] = acc;
        }
        float4 y;
        y.x = t[0]; y.y = t[1]; y.z = t[2]; y.w = t[3];
        out[(size_t)rr * 4 + q] = y;
    }
}

// ---------------------------------------------------------------------------
extern "C" void kernel_launch(void* const* d_in, const int* in_sizes, int n_in,
                              void* d_out, int out_size) {
    const float* left    = (const float*)d_in[0];
    const float* efeat   = (const float*)d_in[1];
    const float* right   = (const float*)d_in[2];
    const int*   eidx    = (const int*)d_in[3];   // int32: JAX x64 disabled
    const float* W_left  = (const float*)d_in[4];
    const float* b_left  = (const float*)d_in[5];
    const float* W_edge  = (const float*)d_in[6];
    const float* W_right = (const float*)d_in[7];
    const float* W_final = (const float*)d_in[8];
    const float* b_final = (const float*)d_in[9];
    const float* W_post  = (const float*)d_in[10];
    const float* b_post  = (const float*)d_in[11];
    const float* W_out1  = (const float*)d_in[12];
    const float* b_out1  = (const float*)d_in[13];
    const float* W_out2  = (const float*)d_in[14];
    const float* b_out2  = (const float*)d_in[15];
    float* out = (float*)d_out;

    int n_left  = in_sizes[0] / EMB;
    int n_right = in_sizes[2] / EMB;
    int E       = in_sizes[1];

    int total_threads = n_left + n_right + n_right;   // nodes + zero-init range
    node_transform_kernel<<<(total_threads + 255) / 256, 256>>>(
        (const float4*)left, (const float4*)right, (const float4*)W_left, b_left,
        (const float4*)W_right, W_post, b_post, W_out1, b_out1,
        n_left, n_right);

    long long edge_threads = (long long)E * 2;
    int edge_blocks = (int)((edge_threads + 255) / 256);
    edge_kernel<<<edge_blocks, 256>>>(eidx, efeat, (const float4*)W_edge, E);

    post_kernel<<<(n_right + 127) / 128, 128>>>(
        (const float4*)right,
        (const float4*)W_final, b_final,
        W_out1,
        (const float4*)W_out2, b_out2,
        (float4*)out, n_right);
}